// round 8
// baseline (speedup 1.0000x reference)
#include <cuda_runtime.h>
#include <cooperative_groups.h>
#include <cstdint>

namespace cg = cooperative_groups;

#define D        32
#define HID      128
#define GRID_G   64
#define NN       4096
#define BB       8
#define TOTAL    (BB*NN)   // 32768 nodes
#define ROW      80        // floats per node row
#define NT       32        // nodes per sub-tile
#define XSTR     68        // X smem row stride (floats)
#define NCTA     512       // persistent grid (2 sub-tiles per CTA)

// xi-contribution scratch: C[net][node][j] (includes b1)
__device__ float g_C[2][TOTAL * HID];

// ---- packed f32x2 helpers ----
#define FMA2(d, a, b, c) \
    asm("fma.rn.f32x2 %0, %1, %2, %3;" : "=l"(d) : "l"(a), "l"(b), "l"(c))
#define ADD2(d, a, b) \
    asm("add.rn.f32x2 %0, %1, %2;" : "=l"(d) : "l"(a), "l"(b))
#define PACK2(d, lo, hi) \
    asm("mov.b64 %0, {%1, %2};" : "=l"(d) : "f"(lo), "f"(hi))
#define UNPACK2(lo, hi, s) \
    asm("mov.b64 {%0, %1}, %2;" : "=f"(lo), "=f"(hi) : "l"(s))

__device__ __forceinline__ float tanh_fast(float x) {
    float e = __expf(x + x);
    return 1.0f - __fdividef(2.0f, e + 1.0f);
}

// ---------------------------------------------------------------------------
// Precompute C[which][n][j] = b1[j] + sum_k xi[n][k] * W1[64+k][j]
// ---------------------------------------------------------------------------
__global__ void __launch_bounds__(128)
precompute_C_kernel(const float* __restrict__ x,
                    const float* __restrict__ W1,
                    const float* __restrict__ b1,
                    int which)
{
    __shared__ float W1cs[16 * HID];  // [j][k]
    __shared__ float b1s[HID];
    const int tid = threadIdx.x;
    for (int idx = tid; idx < 16 * HID; idx += 128) {
        int k = idx >> 7, j = idx & 127;
        W1cs[j * 16 + k] = W1[(64 + k) * HID + j];
    }
    if (tid < HID) b1s[tid] = b1[tid];
    __syncthreads();

    const int n = blockIdx.x * 128 + tid;
    const float4* xiv = (const float4*)(x + (size_t)n * ROW + 2 * D);
    unsigned long long xp8[8];
    #pragma unroll
    for (int i = 0; i < 4; i++) {
        float4 v = xiv[i];
        PACK2(xp8[2 * i],     v.x, v.y);
        PACK2(xp8[2 * i + 1], v.z, v.w);
    }
    float* Crow = g_C[which] + (size_t)n * HID;
    for (int jb = 0; jb < 32; jb++) {
        float s[4];
        #pragma unroll
        for (int jj = 0; jj < 4; jj++) {
            int j = jb * 4 + jj;
            const ulonglong2* wp = (const ulonglong2*)(W1cs + j * 16);
            unsigned long long a0 = 0ull, a1 = 0ull;
            #pragma unroll
            for (int u = 0; u < 4; u++) {
                ulonglong2 w = wp[u];
                FMA2(a0, xp8[2 * u],     w.x, a0);
                FMA2(a1, xp8[2 * u + 1], w.y, a1);
            }
            ADD2(a0, a0, a1);
            float lo, hi;
            UNPACK2(lo, hi, a0);
            s[jj] = lo + hi + b1s[j];
        }
        *(float4*)(Crow + jb * 4) = make_float4(s[0], s[1], s[2], s[3]);
    }
}

// ---------------------------------------------------------------------------
// Persistent cooperative solver. One wave (512 CTAs x 128 thr, 4/SM).
// Per phase: weights->regs; per 32-node sub-tile: stage C, gather X,
// GEMM1+tanh, GEMM2 (strip rotation), writeback. grid.sync() between phases.
// ---------------------------------------------------------------------------
__global__ void __launch_bounds__(128, 4)
solver_kernel(float* __restrict__ state,
              const float* __restrict__ tfin,
              const float* __restrict__ W1q_, const float* __restrict__ W2q_,
              const float* __restrict__ b2q_,
              const float* __restrict__ W1p_, const float* __restrict__ W2p_,
              const float* __restrict__ b2p_)
{
    __shared__ float Xs[NT * XSTR];      // 2176 floats
    __shared__ float Hs[NT * HID];       // 4096 floats
    __shared__ float Ps[2 * NT * D];     // 2048 floats
    __shared__ float Cs[NT * HID];       // 4096 floats

    cg::grid_group grid = cg::this_grid();
    const int tid = threadIdx.x;
    const int j   = tid;

    for (int k = 0; k < 18; k++) {
        #pragma unroll 1
        for (int phase = 0; phase < 2; phase++) {
            const float* W1 = phase ? W1p_ : W1q_;
            const float* W2 = phase ? W2p_ : W2q_;
            const float* b2 = phase ? b2p_ : b2q_;
            const int which = phase;
            const int zoff  = phase ? 0 : D;   // q-phase reads p; p-phase reads q
            const int toff  = phase ? D : 0;
            float tstart, dtmax;
            if (phase == 0) {
                tstart = (k == 0) ? 0.0f : (0.125f + (k - 1) * 0.25f);
                dtmax  = (k == 0) ? 0.125f : 0.25f;
            } else {
                tstart = k * 0.25f;
                dtmax  = 0.25f;
            }

            // per-phase weight load (L2-hit after first phase)
            unsigned long long w1p[32];
            #pragma unroll
            for (int i = 0; i < 32; i++)
                PACK2(w1p[i], W1[(2 * i) * HID + j], W1[(2 * i + 1) * HID + j]);

            #pragma unroll 1
            for (int sub = 0; sub < 2; sub++) {
                const int node_base = blockIdx.x * (2 * NT) + sub * NT;

                // ---- stage C tile (coalesced float4) ----
                {
                    const float4* Cbase =
                        (const float4*)(g_C[which] + (size_t)node_base * HID);
                    float4* Cdst = (float4*)Cs;
                    #pragma unroll
                    for (int i = 0; i < (NT * HID / 4) / 128; i++)
                        Cdst[i * 128 + tid] = Cbase[i * 128 + tid];
                }

                // ---- gather X = [z | mean_nbr] ----
                {
                    const int n    = tid >> 2;
                    const int part = tid & 3;
                    const int node = node_base + n;
                    const int nn_  = node & (NN - 1);
                    const int r = nn_ >> 6, c = nn_ & (GRID_G - 1);
                    const float* rowbase = state + (size_t)(node - nn_) * ROW;

                    if (part < 2) {
                        const float4* src = (const float4*)
                            (state + (size_t)node * ROW + zoff + part * 16);
                        float4* dst = (float4*)(Xs + n * XSTR + part * 16);
                        #pragma unroll
                        for (int i = 0; i < 4; i++) dst[i] = src[i];
                    } else {
                        const int nu = (((r + GRID_G - 1) & (GRID_G - 1)) << 6) | c;
                        const int nd = (((r + 1) & (GRID_G - 1)) << 6) | c;
                        const int nl = (r << 6) | ((c + GRID_G - 1) & (GRID_G - 1));
                        const int nr = (r << 6) | ((c + 1) & (GRID_G - 1));
                        const int koff = (part - 2) * 16;
                        const float4* pu = (const float4*)(rowbase + (size_t)nu * ROW + zoff + koff);
                        const float4* pd = (const float4*)(rowbase + (size_t)nd * ROW + zoff + koff);
                        const float4* pl = (const float4*)(rowbase + (size_t)nl * ROW + zoff + koff);
                        const float4* pr = (const float4*)(rowbase + (size_t)nr * ROW + zoff + koff);
                        float4* dst = (float4*)(Xs + n * XSTR + 32 + koff);
                        #pragma unroll
                        for (int i = 0; i < 4; i++) {
                            float4 a = pu[i], b = pd[i], e = pl[i], f = pr[i];
                            float4 m;
                            m.x = 0.25f * (a.x + b.x + e.x + f.x);
                            m.y = 0.25f * (a.y + b.y + e.y + f.y);
                            m.z = 0.25f * (a.z + b.z + e.z + f.z);
                            m.w = 0.25f * (a.w + b.w + e.w + f.w);
                            dst[i] = m;
                        }
                    }
                }
                __syncthreads();

                // ---- GEMM1 + tanh ----
                #pragma unroll 2
                for (int n = 0; n < NT; n++) {
                    float cv = Cs[n * HID + j];
                    const ulonglong2* xr = (const ulonglong2*)(Xs + n * XSTR);
                    unsigned long long a0 = 0ull, a1 = 0ull, a2 = 0ull, a3 = 0ull;
                    #pragma unroll
                    for (int i = 0; i < 16; i += 2) {
                        ulonglong2 u = xr[i];
                        ulonglong2 v = xr[i + 1];
                        FMA2(a0, u.x, w1p[2 * i],     a0);
                        FMA2(a1, u.y, w1p[2 * i + 1], a1);
                        FMA2(a2, v.x, w1p[2 * i + 2], a2);
                        FMA2(a3, v.y, w1p[2 * i + 3], a3);
                    }
                    ADD2(a0, a0, a1);
                    ADD2(a2, a2, a3);
                    ADD2(a0, a0, a2);
                    float lo, hi;
                    UNPACK2(lo, hi, a0);
                    Hs[n * HID + j] = tanh_fast(lo + hi + cv);
                }
                __syncthreads();

                // ---- GEMM2: W2 quarter in regs, strip rotation ----
                {
                    const int dlane = tid & 31;
                    const int w     = tid >> 5;
                    const int pb    = w >> 1;

                    unsigned long long w2p[16];
                    #pragma unroll
                    for (int i = 0; i < 16; i++) {
                        int jj = w * 32 + 2 * i;
                        PACK2(w2p[i], W2[jj * D + dlane], W2[(jj + 1) * D + dlane]);
                    }

                    for (int s = 0; s < 2; s++) {
                        const int st = (w + s) & 1;
                        const int n0 = st * 16;
                        #pragma unroll 2
                        for (int n = n0; n < n0 + 16; n++) {
                            const ulonglong2* hr =
                                (const ulonglong2*)(Hs + n * HID + w * 32);
                            unsigned long long a0 = 0ull, a1 = 0ull;
                            #pragma unroll
                            for (int i = 0; i < 8; i += 2) {
                                ulonglong2 u = hr[i];
                                ulonglong2 v = hr[i + 1];
                                FMA2(a0, u.x, w2p[2 * i],     a0);
                                FMA2(a1, u.y, w2p[2 * i + 1], a1);
                                FMA2(a0, v.x, w2p[2 * i + 2], a0);
                                FMA2(a1, v.y, w2p[2 * i + 3], a1);
                            }
                            ADD2(a0, a0, a1);
                            float lo, hi;
                            UNPACK2(lo, hi, a0);
                            float val = lo + hi;
                            float* pp = Ps + pb * (NT * D) + n * D + dlane;
                            if (s == 0) *pp = val;
                            else        *pp += val;
                        }
                        __syncthreads();
                    }
                }

                // ---- writeback: z += dt * (P0 + P1 + b2) ----
                {
                    const int bcta = node_base >> 12;
                    float tfv = __ldg(tfin + bcta);
                    float dtv = fminf(fmaxf(tfv - tstart, 0.0f), dtmax);
                    #pragma unroll
                    for (int rix = 0; rix < 8; rix++) {
                        int idx = rix * 128 + tid;
                        int n = idx >> 5, dd = idx & 31;
                        float val = Ps[n * D + dd] + Ps[NT * D + n * D + dd]
                                  + __ldg(b2 + dd);
                        float* gp = state + (size_t)(node_base + n) * ROW + toff + dd;
                        *gp += dtv * val;
                    }
                }
                __syncthreads();
            }

            // order this phase's writes before next phase's gathers
            if (!(k == 17 && phase == 1))
                grid.sync();
        }
    }
}

extern "C" void kernel_launch(void* const* d_in, const int* in_sizes, int n_in,
                              void* d_out, int out_size)
{
    const float* x    = (const float*)d_in[0];
    const float* tf   = (const float*)d_in[1];
    const float* W1q  = (const float*)d_in[2];
    const float* b1q  = (const float*)d_in[3];
    const float* W2q  = (const float*)d_in[4];
    const float* b2q  = (const float*)d_in[5];
    const float* W1p  = (const float*)d_in[6];
    const float* b1p  = (const float*)d_in[7];
    const float* W2p  = (const float*)d_in[8];
    const float* b2p  = (const float*)d_in[9];
    float* state = (float*)d_out;

    cudaMemcpyAsync(state, x, (size_t)out_size * sizeof(float),
                    cudaMemcpyDeviceToDevice);

    precompute_C_kernel<<<TOTAL / 128, 128>>>(x, W1q, b1q, 0);
    precompute_C_kernel<<<TOTAL / 128, 128>>>(x, W1p, b1p, 1);

    // persistent cooperative solver: single wave, grid barrier between phases
    cudaLaunchConfig_t cfg = {};
    cfg.gridDim  = dim3(NCTA, 1, 1);
    cfg.blockDim = dim3(128, 1, 1);
    cfg.dynamicSmemBytes = 0;
    cfg.stream = 0;
    cudaLaunchAttribute attr[1];
    attr[0].id = cudaLaunchAttributeCooperative;
    attr[0].val.cooperative = 1;
    cfg.attrs = attr;
    cfg.numAttrs = 1;
    cudaLaunchKernelEx(&cfg, solver_kernel,
                       state, tf, W1q, W2q, b2q, W1p, W2p, b2p);

    (void)in_sizes; (void)n_in;
}

// round 10
// speedup vs baseline: 1.0272x; 1.0272x over previous
#include <cuda_runtime.h>
#include <cstdint>

#define D        32
#define HID      128
#define GRID_G   64
#define NN       4096
#define BB       8
#define TOTAL    (BB*NN)   // 32768 nodes
#define ROW      80        // floats per node row
#define NT       32        // nodes per sub-tile
#define XSTR     68        // X smem row stride (floats)
#define NCTA     512       // 2 sub-tiles per CTA -> single wave (<=592 slots)

// xi-contribution scratch: C[net][node][j] (includes b1)
__device__ float g_C[2][TOTAL * HID];

// ---- packed f32x2 helpers ----
#define FMA2(d, a, b, c) \
    asm("fma.rn.f32x2 %0, %1, %2, %3;" : "=l"(d) : "l"(a), "l"(b), "l"(c))
#define ADD2(d, a, b) \
    asm("add.rn.f32x2 %0, %1, %2;" : "=l"(d) : "l"(a), "l"(b))
#define PACK2(d, lo, hi) \
    asm("mov.b64 %0, {%1, %2};" : "=l"(d) : "f"(lo), "f"(hi))
#define UNPACK2(lo, hi, s) \
    asm("mov.b64 {%0, %1}, %2;" : "=f"(lo), "=f"(hi) : "l"(s))

__device__ __forceinline__ float tanh_fast(float x) {
    float e = __expf(x + x);
    return 1.0f - __fdividef(2.0f, e + 1.0f);
}

// ---------------------------------------------------------------------------
// Precompute C[which][n][j] = b1[j] + sum_k xi[n][k] * W1[64+k][j]
// ---------------------------------------------------------------------------
__global__ void __launch_bounds__(128)
precompute_C_kernel(const float* __restrict__ x,
                    const float* __restrict__ W1,
                    const float* __restrict__ b1,
                    int which)
{
    __shared__ float W1cs[16 * HID];  // [j][k]
    __shared__ float b1s[HID];
    const int tid = threadIdx.x;
    for (int idx = tid; idx < 16 * HID; idx += 128) {
        int k = idx >> 7, j = idx & 127;
        W1cs[j * 16 + k] = W1[(64 + k) * HID + j];
    }
    if (tid < HID) b1s[tid] = b1[tid];
    __syncthreads();

    const int n = blockIdx.x * 128 + tid;
    const float4* xiv = (const float4*)(x + (size_t)n * ROW + 2 * D);
    unsigned long long xp8[8];
    #pragma unroll
    for (int i = 0; i < 4; i++) {
        float4 v = xiv[i];
        PACK2(xp8[2 * i],     v.x, v.y);
        PACK2(xp8[2 * i + 1], v.z, v.w);
    }
    float* Crow = g_C[which] + (size_t)n * HID;
    for (int jb = 0; jb < 32; jb++) {
        float s[4];
        #pragma unroll
        for (int jj = 0; jj < 4; jj++) {
            int j = jb * 4 + jj;
            const ulonglong2* wp = (const ulonglong2*)(W1cs + j * 16);
            unsigned long long a0 = 0ull, a1 = 0ull;
            #pragma unroll
            for (int u = 0; u < 4; u++) {
                ulonglong2 w = wp[u];
                FMA2(a0, xp8[2 * u],     w.x, a0);
                FMA2(a1, xp8[2 * u + 1], w.y, a1);
            }
            ADD2(a0, a0, a1);
            float lo, hi;
            UNPACK2(lo, hi, a0);
            s[jj] = lo + hi + b1s[j];
        }
        *(float4*)(Crow + jb * 4) = make_float4(s[0], s[1], s[2], s[3]);
    }
}

// ---------------------------------------------------------------------------
// Half-update, weight-stationary, single-wave grid (512 CTAs, 2 sub-tiles):
//   prologue: W1 column -> regs (amortized over 64 nodes).
//   per sub-tile: stage C -> smem, gather X, GEMM1+tanh, GEMM2, writeback.
// ---------------------------------------------------------------------------
__global__ void __launch_bounds__(128, 4)
half_step_kernel(float* __restrict__ state,
                 const float* __restrict__ tfin,
                 const float* __restrict__ W1,   // (80,128) k-major
                 const float* __restrict__ W2,   // (128,32) j-major
                 const float* __restrict__ b2,   // (32)
                 int which,
                 int zoff, int toff,
                 float tstart, float dtmax)
{
    __shared__ float Xs[NT * XSTR];      // 2176 floats
    __shared__ float Hs[NT * HID];       // 4096 floats
    __shared__ float Ps[2 * NT * D];     // 2048 floats
    __shared__ float Cs[NT * HID];       // 4096 floats

    const int tid = threadIdx.x;
    const int j   = tid;

    // prologue: W1 column in regs, reused for both sub-tiles
    unsigned long long w1p[32];
    #pragma unroll
    for (int i = 0; i < 32; i++)
        PACK2(w1p[i], W1[(2 * i) * HID + j], W1[(2 * i + 1) * HID + j]);

    #pragma unroll 1
    for (int sub = 0; sub < 2; sub++) {
        const int node_base = blockIdx.x * (2 * NT) + sub * NT;

        // ---- stage C tile (coalesced float4) ----
        {
            const float4* Cbase =
                (const float4*)(g_C[which] + (size_t)node_base * HID);
            float4* Cdst = (float4*)Cs;
            #pragma unroll
            for (int i = 0; i < (NT * HID / 4) / 128; i++)
                Cdst[i * 128 + tid] = Cbase[i * 128 + tid];
        }

        // ---- gather X = [z | mean_nbr] ----
        {
            const int n    = tid >> 2;
            const int part = tid & 3;
            const int node = node_base + n;
            const int nn_  = node & (NN - 1);
            const int r = nn_ >> 6, c = nn_ & (GRID_G - 1);
            const float* rowbase = state + (size_t)(node - nn_) * ROW;

            if (part < 2) {
                const float4* src = (const float4*)
                    (state + (size_t)node * ROW + zoff + part * 16);
                float4* dst = (float4*)(Xs + n * XSTR + part * 16);
                #pragma unroll
                for (int i = 0; i < 4; i++) dst[i] = src[i];
            } else {
                const int nu = (((r + GRID_G - 1) & (GRID_G - 1)) << 6) | c;
                const int nd = (((r + 1) & (GRID_G - 1)) << 6) | c;
                const int nl = (r << 6) | ((c + GRID_G - 1) & (GRID_G - 1));
                const int nr = (r << 6) | ((c + 1) & (GRID_G - 1));
                const int koff = (part - 2) * 16;
                const float4* pu = (const float4*)(rowbase + (size_t)nu * ROW + zoff + koff);
                const float4* pd = (const float4*)(rowbase + (size_t)nd * ROW + zoff + koff);
                const float4* pl = (const float4*)(rowbase + (size_t)nl * ROW + zoff + koff);
                const float4* pr = (const float4*)(rowbase + (size_t)nr * ROW + zoff + koff);
                float4* dst = (float4*)(Xs + n * XSTR + 32 + koff);
                #pragma unroll
                for (int i = 0; i < 4; i++) {
                    float4 a = pu[i], b = pd[i], e = pl[i], f = pr[i];
                    float4 m;
                    m.x = 0.25f * (a.x + b.x + e.x + f.x);
                    m.y = 0.25f * (a.y + b.y + e.y + f.y);
                    m.z = 0.25f * (a.z + b.z + e.z + f.z);
                    m.w = 0.25f * (a.w + b.w + e.w + f.w);
                    dst[i] = m;
                }
            }
        }
        __syncthreads();

        // ---- GEMM1 + tanh ----
        #pragma unroll 2
        for (int n = 0; n < NT; n++) {
            float cv = Cs[n * HID + j];
            const ulonglong2* xr = (const ulonglong2*)(Xs + n * XSTR);
            unsigned long long a0 = 0ull, a1 = 0ull, a2 = 0ull, a3 = 0ull;
            #pragma unroll
            for (int i = 0; i < 16; i += 2) {
                ulonglong2 u = xr[i];
                ulonglong2 v = xr[i + 1];
                FMA2(a0, u.x, w1p[2 * i],     a0);
                FMA2(a1, u.y, w1p[2 * i + 1], a1);
                FMA2(a2, v.x, w1p[2 * i + 2], a2);
                FMA2(a3, v.y, w1p[2 * i + 3], a3);
            }
            ADD2(a0, a0, a1);
            ADD2(a2, a2, a3);
            ADD2(a0, a0, a2);
            float lo, hi;
            UNPACK2(lo, hi, a0);
            Hs[n * HID + j] = tanh_fast(lo + hi + cv);
        }
        __syncthreads();

        // ---- GEMM2: W2 quarter in regs, strip rotation ----
        {
            const int dlane = tid & 31;
            const int w     = tid >> 5;
            const int pb    = w >> 1;

            unsigned long long w2p[16];
            #pragma unroll
            for (int i = 0; i < 16; i++) {
                int jj = w * 32 + 2 * i;
                PACK2(w2p[i], W2[jj * D + dlane], W2[(jj + 1) * D + dlane]);
            }

            for (int s = 0; s < 2; s++) {
                const int st = (w + s) & 1;
                const int n0 = st * 16;
                #pragma unroll 2
                for (int n = n0; n < n0 + 16; n++) {
                    const ulonglong2* hr =
                        (const ulonglong2*)(Hs + n * HID + w * 32);
                    unsigned long long a0 = 0ull, a1 = 0ull;
                    #pragma unroll
                    for (int i = 0; i < 8; i += 2) {
                        ulonglong2 u = hr[i];
                        ulonglong2 v = hr[i + 1];
                        FMA2(a0, u.x, w2p[2 * i],     a0);
                        FMA2(a1, u.y, w2p[2 * i + 1], a1);
                        FMA2(a0, v.x, w2p[2 * i + 2], a0);
                        FMA2(a1, v.y, w2p[2 * i + 3], a1);
                    }
                    ADD2(a0, a0, a1);
                    float lo, hi;
                    UNPACK2(lo, hi, a0);
                    float val = lo + hi;
                    float* pp = Ps + pb * (NT * D) + n * D + dlane;
                    if (s == 0) *pp = val;
                    else        *pp += val;
                }
                __syncthreads();
            }
        }

        // ---- writeback: z += dt * (P0 + P1 + b2) ----
        {
            const int bcta = node_base >> 12;
            float tfv = __ldg(tfin + bcta);
            float dtv = fminf(fmaxf(tfv - tstart, 0.0f), dtmax);
            #pragma unroll
            for (int rix = 0; rix < 8; rix++) {
                int idx = rix * 128 + tid;
                int n = idx >> 5, dd = idx & 31;
                float val = Ps[n * D + dd] + Ps[NT * D + n * D + dd]
                          + __ldg(b2 + dd);
                float* gp = state + (size_t)(node_base + n) * ROW + toff + dd;
                *gp += dtv * val;
            }
        }
        __syncthreads();
    }
}

extern "C" void kernel_launch(void* const* d_in, const int* in_sizes, int n_in,
                              void* d_out, int out_size)
{
    const float* x    = (const float*)d_in[0];
    const float* tf   = (const float*)d_in[1];
    const float* W1q  = (const float*)d_in[2];
    const float* b1q  = (const float*)d_in[3];
    const float* W2q  = (const float*)d_in[4];
    const float* b2q  = (const float*)d_in[5];
    const float* W1p  = (const float*)d_in[6];
    const float* b1p  = (const float*)d_in[7];
    const float* W2p  = (const float*)d_in[8];
    const float* b2p  = (const float*)d_in[9];
    float* state = (float*)d_out;

    cudaMemcpyAsync(state, x, (size_t)out_size * sizeof(float),
                    cudaMemcpyDeviceToDevice);

    precompute_C_kernel<<<TOTAL / 128, 128>>>(x, W1q, b1q, 0);
    precompute_C_kernel<<<TOTAL / 128, 128>>>(x, W1p, b1p, 1);

    const float DT = 0.25f;

    for (int k = 0; k < 18; k++) {
        float tsq = (k == 0) ? 0.0f : (0.125f + (k - 1) * DT);
        float dmq = (k == 0) ? 0.125f : DT;
        half_step_kernel<<<NCTA, 128>>>(
            state, tf, W1q, W2q, b2q, /*which=*/0,
            /*zoff=*/D, /*toff=*/0, tsq, dmq);

        float tsp = k * DT;
        half_step_kernel<<<NCTA, 128>>>(
            state, tf, W1p, W2p, b2p, /*which=*/1,
            /*zoff=*/0, /*toff=*/D, tsp, DT);
    }
    (void)in_sizes; (void)n_in;
}

// round 15
// speedup vs baseline: 1.9506x; 1.8990x over previous
#include <cuda_runtime.h>
#include <cuda_bf16.h>
#include <cstdint>

#define D        32
#define HID      128
#define GRID_G   64
#define NN       4096
#define BB       8
#define TOTAL    (BB*NN)   // 32768 nodes
#define ROW      80
#define MT       64        // nodes per CTA
#define NCTA     (TOTAL/MT) // 512 -> single wave

// ---- smem byte offsets (overlayed phases) ----
#define XH_OFF   0          // X hi  [64 rows x 144B]
#define XL_OFF   9216       // X lo
#define W1H_OFF  18432      // W1^T hi [128 x 144B]
#define W1L_OFF  36864      // W1^T lo
// phase 2 overlays (X/W1 dead after GEMM1):
#define HH_OFF   0          // H hi [64 x 272B]
#define HL_OFF   17408      // H lo
#define W2H_OFF  34816      // W2^T hi [32 x 272B]
#define W2L_OFF  43520      // W2^T lo
#define SMEM_BYTES 55296
#define XSTR     144
#define W1STR    144
#define HSTR     272
#define W2STR    272

// xi-contribution scratch: C[net][node][j] (includes b1)
__device__ float g_C[2][TOTAL * HID];

// ---- packed f32x2 helpers (precompute kernel only) ----
#define FMA2(d, a, b, c) \
    asm("fma.rn.f32x2 %0, %1, %2, %3;" : "=l"(d) : "l"(a), "l"(b), "l"(c))
#define ADD2(d, a, b) \
    asm("add.rn.f32x2 %0, %1, %2;" : "=l"(d) : "l"(a), "l"(b))
#define PACK2(d, lo, hi) \
    asm("mov.b64 %0, {%1, %2};" : "=l"(d) : "f"(lo), "f"(hi))
#define UNPACK2(lo, hi, s) \
    asm("mov.b64 {%0, %1}, %2;" : "=f"(lo), "=f"(hi) : "l"(s))

__device__ __forceinline__ float tanh_fast(float x) {
    float e = __expf(x + x);
    return 1.0f - __fdividef(2.0f, e + 1.0f);
}

// mma.sync m16n8k16 bf16 x bf16 -> f32 accumulate (sm_80+, valid on compute_103)
__device__ __forceinline__ void mma_bf16(float c[4], const uint32_t a[4],
                                         const uint32_t b[2])
{
    asm volatile(
        "mma.sync.aligned.m16n8k16.row.col.f32.bf16.bf16.f32 "
        "{%0,%1,%2,%3}, {%4,%5,%6,%7}, {%8,%9}, {%0,%1,%2,%3};"
        : "+f"(c[0]), "+f"(c[1]), "+f"(c[2]), "+f"(c[3])
        : "r"(a[0]), "r"(a[1]), "r"(a[2]), "r"(a[3]),
          "r"(b[0]), "r"(b[1]));
}

// split fp32 pair into bf16 hi/lo b32 words, store to smem
__device__ __forceinline__ void sts_split(char* sm, int hioff, int looff,
                                          float a, float b)
{
    __nv_bfloat16 ah = __float2bfloat16(a);
    __nv_bfloat16 bh = __float2bfloat16(b);
    __nv_bfloat162 hi(ah, bh);
    __nv_bfloat162 lo(__float2bfloat16(a - __bfloat162float(ah)),
                      __float2bfloat16(b - __bfloat162float(bh)));
    *reinterpret_cast<uint32_t*>(sm + hioff) = *reinterpret_cast<uint32_t*>(&hi);
    *reinterpret_cast<uint32_t*>(sm + looff) = *reinterpret_cast<uint32_t*>(&lo);
}

__device__ __forceinline__ uint32_t lds32(const char* sm, int off) {
    return *reinterpret_cast<const uint32_t*>(sm + off);
}

// ---------------------------------------------------------------------------
// Precompute C[which][n][j] = b1[j] + sum_k xi[n][k] * W1[64+k][j]  (fp32)
// ---------------------------------------------------------------------------
__global__ void __launch_bounds__(128)
precompute_C_kernel(const float* __restrict__ x,
                    const float* __restrict__ W1,
                    const float* __restrict__ b1,
                    int which)
{
    __shared__ float W1cs[16 * HID];
    __shared__ float b1s[HID];
    const int tid = threadIdx.x;
    for (int idx = tid; idx < 16 * HID; idx += 128) {
        int k = idx >> 7, j = idx & 127;
        W1cs[j * 16 + k] = W1[(64 + k) * HID + j];
    }
    if (tid < HID) b1s[tid] = b1[tid];
    __syncthreads();

    const int n = blockIdx.x * 128 + tid;
    const float4* xiv = (const float4*)(x + (size_t)n * ROW + 2 * D);
    unsigned long long xp8[8];
    #pragma unroll
    for (int i = 0; i < 4; i++) {
        float4 v = xiv[i];
        PACK2(xp8[2 * i],     v.x, v.y);
        PACK2(xp8[2 * i + 1], v.z, v.w);
    }
    float* Crow = g_C[which] + (size_t)n * HID;
    for (int jb = 0; jb < 32; jb++) {
        float s[4];
        #pragma unroll
        for (int jj = 0; jj < 4; jj++) {
            int j = jb * 4 + jj;
            const ulonglong2* wp = (const ulonglong2*)(W1cs + j * 16);
            unsigned long long a0 = 0ull, a1 = 0ull;
            #pragma unroll
            for (int u = 0; u < 4; u++) {
                ulonglong2 w = wp[u];
                FMA2(a0, xp8[2 * u],     w.x, a0);
                FMA2(a1, xp8[2 * u + 1], w.y, a1);
            }
            ADD2(a0, a0, a1);
            float lo, hi;
            UNPACK2(lo, hi, a0);
            s[jj] = lo + hi + b1s[j];
        }
        *(float4*)(Crow + jb * 4) = make_float4(s[0], s[1], s[2], s[3]);
    }
}

// ---------------------------------------------------------------------------
// Half-step via warp MMA (bf16 3-product split), 64-node tile per CTA.
// ---------------------------------------------------------------------------
__global__ void __launch_bounds__(128)
half_step_mma(float* __restrict__ state,
              const float* __restrict__ tfin,
              const float* __restrict__ W1,   // (80,128) k-major
              const float* __restrict__ W2,   // (128,32) j-major
              const float* __restrict__ b2,   // (32)
              int which, int zoff, int toff,
              float tstart, float dtmax)
{
    extern __shared__ char sm[];
    const int tid  = threadIdx.x;
    const int wid  = tid >> 5;
    const int lane = tid & 31;
    const int lr   = lane >> 2;    // 0..7
    const int lq   = lane & 3;     // 0..3
    const int node_base = blockIdx.x * MT;

    // ---- stage W1^T hi/lo: row j = tid, k pairs ----
    #pragma unroll 8
    for (int k2 = 0; k2 < 64; k2 += 2) {
        float a = __ldg(W1 + k2 * HID + tid);
        float b = __ldg(W1 + (k2 + 1) * HID + tid);
        sts_split(sm, W1H_OFF + tid * W1STR + k2 * 2,
                      W1L_OFF + tid * W1STR + k2 * 2, a, b);
    }

    // ---- gather X = [z(32) | mean_nbr(32)], split hi/lo (2 thr/node) ----
    {
        const int n = tid >> 1, half = tid & 1;
        const int node = node_base + n;
        const int nn_ = node & (NN - 1);
        const int r = nn_ >> 6, c = nn_ & (GRID_G - 1);
        const float* bp = state + (size_t)(node - nn_) * ROW;
        float v[32];
        if (half == 0) {
            const float4* pZ = (const float4*)(bp + (size_t)nn_ * ROW + zoff);
            #pragma unroll
            for (int i = 0; i < 8; i++) {
                float4 o = __ldg(pZ + i);
                v[4 * i] = o.x; v[4 * i + 1] = o.y;
                v[4 * i + 2] = o.z; v[4 * i + 3] = o.w;
            }
        } else {
            const int nu = (((r + GRID_G - 1) & (GRID_G - 1)) << 6) | c;
            const int nd = (((r + 1) & (GRID_G - 1)) << 6) | c;
            const int nl = (r << 6) | ((c + GRID_G - 1) & (GRID_G - 1));
            const int nr = (r << 6) | ((c + 1) & (GRID_G - 1));
            const float4* pU = (const float4*)(bp + (size_t)nu * ROW + zoff);
            const float4* pD = (const float4*)(bp + (size_t)nd * ROW + zoff);
            const float4* pL = (const float4*)(bp + (size_t)nl * ROW + zoff);
            const float4* pR = (const float4*)(bp + (size_t)nr * ROW + zoff);
            #pragma unroll
            for (int i = 0; i < 8; i++) {
                float4 a = __ldg(pU + i), b = __ldg(pD + i);
                float4 e = __ldg(pL + i), f = __ldg(pR + i);
                v[4 * i]     = 0.25f * (a.x + b.x + e.x + f.x);
                v[4 * i + 1] = 0.25f * (a.y + b.y + e.y + f.y);
                v[4 * i + 2] = 0.25f * (a.z + b.z + e.z + f.z);
                v[4 * i + 3] = 0.25f * (a.w + b.w + e.w + f.w);
            }
        }
        #pragma unroll
        for (int i = 0; i < 16; i++)
            sts_split(sm, XH_OFF + n * XSTR + half * 64 + i * 4,
                          XL_OFF + n * XSTR + half * 64 + i * 4,
                          v[2 * i], v[2 * i + 1]);
    }
    __syncthreads();

    // ---- GEMM1: per warp M64 x N32 (n0=wid*32) x K64, 3-product split ----
    float acc[4][4][4];
    #pragma unroll
    for (int a = 0; a < 4; a++)
        #pragma unroll
        for (int b = 0; b < 4; b++)
            #pragma unroll
            for (int cc = 0; cc < 4; cc++) acc[a][b][cc] = 0.0f;

    const int n0 = wid * 32;
    #pragma unroll
    for (int kf = 0; kf < 4; kf++) {
        uint32_t ah[4][4], al[4][4];
        #pragma unroll
        for (int mf = 0; mf < 4; mf++) {
            int base = (mf * 16 + lr) * XSTR + kf * 32 + lq * 4;
            ah[mf][0] = lds32(sm, XH_OFF + base);
            ah[mf][1] = lds32(sm, XH_OFF + base + 8 * XSTR);
            ah[mf][2] = lds32(sm, XH_OFF + base + 16);
            ah[mf][3] = lds32(sm, XH_OFF + base + 8 * XSTR + 16);
            al[mf][0] = lds32(sm, XL_OFF + base);
            al[mf][1] = lds32(sm, XL_OFF + base + 8 * XSTR);
            al[mf][2] = lds32(sm, XL_OFF + base + 16);
            al[mf][3] = lds32(sm, XL_OFF + base + 8 * XSTR + 16);
        }
        #pragma unroll
        for (int nf = 0; nf < 4; nf++) {
            int boff = (n0 + nf * 8 + lr) * W1STR + kf * 32 + lq * 4;
            uint32_t bh[2] = { lds32(sm, W1H_OFF + boff),
                               lds32(sm, W1H_OFF + boff + 16) };
            uint32_t bl[2] = { lds32(sm, W1L_OFF + boff),
                               lds32(sm, W1L_OFF + boff + 16) };
            #pragma unroll
            for (int mf = 0; mf < 4; mf++) {
                mma_bf16(acc[mf][nf], ah[mf], bh);
                mma_bf16(acc[mf][nf], al[mf], bh);
                mma_bf16(acc[mf][nf], ah[mf], bl);
            }
        }
    }
    __syncthreads();   // X/W1 dead; H/W2 will overlay

    // ---- epilogue 1: h = tanh(acc + C) -> H hi/lo smem ----
    #pragma unroll
    for (int mf = 0; mf < 4; mf++) {
        int r_ = mf * 16 + lr;
        const float* Crow0 = g_C[which] + (size_t)(node_base + r_) * HID;
        const float* Crow1 = Crow0 + 8 * HID;
        #pragma unroll
        for (int nf = 0; nf < 4; nf++) {
            int j = n0 + nf * 8 + lq * 2;
            float2 c01 = *(const float2*)(Crow0 + j);
            float2 c23 = *(const float2*)(Crow1 + j);
            float h0 = tanh_fast(acc[mf][nf][0] + c01.x);
            float h1 = tanh_fast(acc[mf][nf][1] + c01.y);
            float h2 = tanh_fast(acc[mf][nf][2] + c23.x);
            float h3 = tanh_fast(acc[mf][nf][3] + c23.y);
            sts_split(sm, HH_OFF + r_ * HSTR + j * 2,
                          HL_OFF + r_ * HSTR + j * 2, h0, h1);
            sts_split(sm, HH_OFF + (r_ + 8) * HSTR + j * 2,
                          HL_OFF + (r_ + 8) * HSTR + j * 2, h2, h3);
        }
    }

    // ---- stage W2^T hi/lo: [d 32][j 128] ----
    {
        const int d_ = tid & 31;
        const int j0 = (tid >> 5) * 32;
        #pragma unroll 4
        for (int jj = 0; jj < 32; jj += 2) {
            float a = __ldg(W2 + (j0 + jj) * D + d_);
            float b = __ldg(W2 + (j0 + jj + 1) * D + d_);
            sts_split(sm, W2H_OFF + d_ * W2STR + (j0 + jj) * 2,
                          W2L_OFF + d_ * W2STR + (j0 + jj) * 2, a, b);
        }
    }
    __syncthreads();

    // ---- GEMM2: per warp M16 (r0=wid*16) x N32 x K128 ----
    float acc2[4][4];
    #pragma unroll
    for (int a = 0; a < 4; a++)
        #pragma unroll
        for (int b = 0; b < 4; b++) acc2[a][b] = 0.0f;

    const int r0 = wid * 16;
    #pragma unroll
    for (int kf = 0; kf < 8; kf++) {
        uint32_t ah[4], al[4];
        int aoff = (r0 + lr) * HSTR + kf * 32 + lq * 4;
        ah[0] = lds32(sm, HH_OFF + aoff);
        ah[1] = lds32(sm, HH_OFF + aoff + 8 * HSTR);
        ah[2] = lds32(sm, HH_OFF + aoff + 16);
        ah[3] = lds32(sm, HH_OFF + aoff + 8 * HSTR + 16);
        al[0] = lds32(sm, HL_OFF + aoff);
        al[1] = lds32(sm, HL_OFF + aoff + 8 * HSTR);
        al[2] = lds32(sm, HL_OFF + aoff + 16);
        al[3] = lds32(sm, HL_OFF + aoff + 8 * HSTR + 16);
        #pragma unroll
        for (int nf = 0; nf < 4; nf++) {
            int boff = (nf * 8 + lr) * W2STR + kf * 32 + lq * 4;
            uint32_t bh[2] = { lds32(sm, W2H_OFF + boff),
                               lds32(sm, W2H_OFF + boff + 16) };
            uint32_t bl[2] = { lds32(sm, W2L_OFF + boff),
                               lds32(sm, W2L_OFF + boff + 16) };
            mma_bf16(acc2[nf], ah, bh);
            mma_bf16(acc2[nf], al, bh);
            mma_bf16(acc2[nf], ah, bl);
        }
    }

    // ---- epilogue 2: state += dt * (acc2 + b2) ----
    {
        float tfv = __ldg(tfin + (node_base >> 12));
        float dtv = fminf(fmaxf(tfv - tstart, 0.0f), dtmax);
        #pragma unroll
        for (int nf = 0; nf < 4; nf++) {
            int d_ = nf * 8 + lq * 2;
            float2 bv = *(const float2*)(b2 + d_);
            int r_ = r0 + lr;
            float* p0 = state + (size_t)(node_base + r_) * ROW + toff + d_;
            float2 cur = *(float2*)p0;
            cur.x += dtv * (acc2[nf][0] + bv.x);
            cur.y += dtv * (acc2[nf][1] + bv.y);
            *(float2*)p0 = cur;
            float* p1 = state + (size_t)(node_base + r_ + 8) * ROW + toff + d_;
            cur = *(float2*)p1;
            cur.x += dtv * (acc2[nf][2] + bv.x);
            cur.y += dtv * (acc2[nf][3] + bv.y);
            *(float2*)p1 = cur;
        }
    }
}

extern "C" void kernel_launch(void* const* d_in, const int* in_sizes, int n_in,
                              void* d_out, int out_size)
{
    const float* x    = (const float*)d_in[0];
    const float* tf   = (const float*)d_in[1];
    const float* W1q  = (const float*)d_in[2];
    const float* b1q  = (const float*)d_in[3];
    const float* W2q  = (const float*)d_in[4];
    const float* b2q  = (const float*)d_in[5];
    const float* W1p  = (const float*)d_in[6];
    const float* b1p  = (const float*)d_in[7];
    const float* W2p  = (const float*)d_in[8];
    const float* b2p  = (const float*)d_in[9];
    float* state = (float*)d_out;

    cudaFuncSetAttribute(half_step_mma,
                         cudaFuncAttributeMaxDynamicSharedMemorySize, SMEM_BYTES);

    cudaMemcpyAsync(state, x, (size_t)out_size * sizeof(float),
                    cudaMemcpyDeviceToDevice);

    precompute_C_kernel<<<TOTAL / 128, 128>>>(x, W1q, b1q, 0);
    precompute_C_kernel<<<TOTAL / 128, 128>>>(x, W1p, b1p, 1);

    const float DT = 0.25f;

    for (int k = 0; k < 18; k++) {
        float tsq = (k == 0) ? 0.0f : (0.125f + (k - 1) * DT);
        float dmq = (k == 0) ? 0.125f : DT;
        half_step_mma<<<NCTA, 128, SMEM_BYTES>>>(
            state, tf, W1q, W2q, b2q, /*which=*/0,
            /*zoff=*/D, /*toff=*/0, tsq, dmq);

        float tsp = k * DT;
        half_step_mma<<<NCTA, 128, SMEM_BYTES>>>(
            state, tf, W1p, W2p, b2p, /*which=*/1,
            /*zoff=*/0, /*toff=*/D, tsp, DT);
    }
    (void)in_sizes; (void)n_in;
}

// round 16
// speedup vs baseline: 2.4339x; 1.2478x over previous
#include <cuda_runtime.h>
#include <cuda_bf16.h>
#include <cstdint>

#define D        32
#define HID      128
#define GRID_G   64
#define NN       4096
#define BB       8
#define TOTAL    (BB*NN)   // 32768 nodes
#define ROW      80
#define MT       64        // nodes per CTA
#define NCTA     (TOTAL/MT) // 512 -> single wave

// ---- smem byte offsets (overlayed phases) ----
#define XH_OFF   0          // X hi  [64 rows x 144B]
#define XL_OFF   9216       // X lo
#define W1H_OFF  18432      // W1^T hi [128 x 144B]
#define W1L_OFF  36864      // W1^T lo
// phase 2 overlays (X/W1 dead after GEMM1):
#define HH_OFF   0          // H hi [64 x 272B]
#define HL_OFF   17408      // H lo
#define W2H_OFF  34816      // W2^T hi [32 x 272B]
#define W2L_OFF  43520      // W2^T lo
#define SMEM_BYTES 55296
#define XSTR     144
#define W1STR    144
#define HSTR     272
#define W2STR    272

#define W1IMG_BYTES 36864   // hi(18432)+lo(18432), byte image of W1 smem region
#define W2IMG_BYTES 17408   // hi(8704)+lo(8704)

// xi-contribution scratch: C[net][node][j] (includes b1)
__device__ float g_C[2][TOTAL * HID];
// pre-split bf16 weight images (byte-identical to smem regions)
__device__ __align__(16) unsigned char g_W1img[2][W1IMG_BYTES];
__device__ __align__(16) unsigned char g_W2img[2][W2IMG_BYTES];

// ---- packed f32x2 helpers (precompute kernel only) ----
#define FMA2(d, a, b, c) \
    asm("fma.rn.f32x2 %0, %1, %2, %3;" : "=l"(d) : "l"(a), "l"(b), "l"(c))
#define ADD2(d, a, b) \
    asm("add.rn.f32x2 %0, %1, %2;" : "=l"(d) : "l"(a), "l"(b))
#define PACK2(d, lo, hi) \
    asm("mov.b64 %0, {%1, %2};" : "=l"(d) : "f"(lo), "f"(hi))
#define UNPACK2(lo, hi, s) \
    asm("mov.b64 {%0, %1}, %2;" : "=f"(lo), "=f"(hi) : "l"(s))

__device__ __forceinline__ float tanh_fast(float x) {
    float e = __expf(x + x);
    return 1.0f - __fdividef(2.0f, e + 1.0f);
}

__device__ __forceinline__ void mma_bf16(float c[4], const uint32_t a[4],
                                         const uint32_t b[2])
{
    asm volatile(
        "mma.sync.aligned.m16n8k16.row.col.f32.bf16.bf16.f32 "
        "{%0,%1,%2,%3}, {%4,%5,%6,%7}, {%8,%9}, {%0,%1,%2,%3};"
        : "+f"(c[0]), "+f"(c[1]), "+f"(c[2]), "+f"(c[3])
        : "r"(a[0]), "r"(a[1]), "r"(a[2]), "r"(a[3]),
          "r"(b[0]), "r"(b[1]));
}

__device__ __forceinline__ void ldmx4(uint32_t r[4], uint32_t addr) {
    asm volatile(
        "ldmatrix.sync.aligned.m8n8.x4.shared.b16 {%0,%1,%2,%3}, [%4];"
        : "=r"(r[0]), "=r"(r[1]), "=r"(r[2]), "=r"(r[3]) : "r"(addr));
}
__device__ __forceinline__ void ldmx2(uint32_t r[2], uint32_t addr) {
    asm volatile(
        "ldmatrix.sync.aligned.m8n8.x2.shared.b16 {%0,%1}, [%2];"
        : "=r"(r[0]), "=r"(r[1]) : "r"(addr));
}

#define CPA16(dst, src) \
    asm volatile("cp.async.cg.shared.global [%0], [%1], 16;" \
        :: "r"(dst), "l"(src) : "memory")
#define CPA_COMMIT() asm volatile("cp.async.commit_group;" ::: "memory")
#define CPA_WAIT0()  asm volatile("cp.async.wait_group 0;" ::: "memory")

__device__ __forceinline__ uint32_t smem_u32(const void* p) {
    uint32_t a;
    asm("{ .reg .u64 t; cvta.to.shared.u64 t, %1; cvt.u32.u64 %0, t; }"
        : "=r"(a) : "l"(p));
    return a;
}

__device__ __forceinline__ uint32_t split_pack(float a, float b, uint32_t& lo32)
{
    __nv_bfloat16 ah = __float2bfloat16(a);
    __nv_bfloat16 bh = __float2bfloat16(b);
    __nv_bfloat162 hi(ah, bh);
    __nv_bfloat162 lo(__float2bfloat16(a - __bfloat162float(ah)),
                      __float2bfloat16(b - __bfloat162float(bh)));
    lo32 = *reinterpret_cast<uint32_t*>(&lo);
    return *reinterpret_cast<uint32_t*>(&hi);
}

__device__ __forceinline__ void sts_split(char* sm, int hioff, int looff,
                                          float a, float b)
{
    uint32_t lo32, hi32 = split_pack(a, b, lo32);
    *reinterpret_cast<uint32_t*>(sm + hioff) = hi32;
    *reinterpret_cast<uint32_t*>(sm + looff) = lo32;
}

// ---------------------------------------------------------------------------
// Precompute C[which][n][j] = b1[j] + sum_k xi[n][k] * W1[64+k][j]  (fp32)
// ---------------------------------------------------------------------------
__global__ void __launch_bounds__(128)
precompute_C_kernel(const float* __restrict__ x,
                    const float* __restrict__ W1,
                    const float* __restrict__ b1,
                    int which)
{
    __shared__ float W1cs[16 * HID];
    __shared__ float b1s[HID];
    const int tid = threadIdx.x;
    for (int idx = tid; idx < 16 * HID; idx += 128) {
        int k = idx >> 7, j = idx & 127;
        W1cs[j * 16 + k] = W1[(64 + k) * HID + j];
    }
    if (tid < HID) b1s[tid] = b1[tid];
    __syncthreads();

    const int n = blockIdx.x * 128 + tid;
    const float4* xiv = (const float4*)(x + (size_t)n * ROW + 2 * D);
    unsigned long long xp8[8];
    #pragma unroll
    for (int i = 0; i < 4; i++) {
        float4 v = xiv[i];
        PACK2(xp8[2 * i],     v.x, v.y);
        PACK2(xp8[2 * i + 1], v.z, v.w);
    }
    float* Crow = g_C[which] + (size_t)n * HID;
    for (int jb = 0; jb < 32; jb++) {
        float s[4];
        #pragma unroll
        for (int jj = 0; jj < 4; jj++) {
            int j = jb * 4 + jj;
            const ulonglong2* wp = (const ulonglong2*)(W1cs + j * 16);
            unsigned long long a0 = 0ull, a1 = 0ull;
            #pragma unroll
            for (int u = 0; u < 4; u++) {
                ulonglong2 w = wp[u];
                FMA2(a0, xp8[2 * u],     w.x, a0);
                FMA2(a1, xp8[2 * u + 1], w.y, a1);
            }
            ADD2(a0, a0, a1);
            float lo, hi;
            UNPACK2(lo, hi, a0);
            s[jj] = lo + hi + b1s[j];
        }
        *(float4*)(Crow + jb * 4) = make_float4(s[0], s[1], s[2], s[3]);
    }
}

// ---------------------------------------------------------------------------
// Setup: pre-split W1/W2 into bf16 hi/lo byte-images of the smem regions.
// blockIdx.x = which (0: q-net, 1: p-net).
// ---------------------------------------------------------------------------
__global__ void __launch_bounds__(128)
setup_weights(const float* __restrict__ W1q, const float* __restrict__ W2q,
              const float* __restrict__ W1p, const float* __restrict__ W2p)
{
    const int which = blockIdx.x;
    const float* W1 = which ? W1p : W1q;
    const float* W2 = which ? W2p : W2q;
    const int tid = threadIdx.x;

    // W1 image: rows j (0..127) x 32 k-pairs, stride 144; lo at +18432
    char* im1 = (char*)g_W1img[which];
    #pragma unroll 4
    for (int k2 = 0; k2 < 32; k2++) {
        float a = __ldg(W1 + (2 * k2) * HID + tid);
        float b = __ldg(W1 + (2 * k2 + 1) * HID + tid);
        uint32_t lo32, hi32 = split_pack(a, b, lo32);
        *(uint32_t*)(im1 + tid * W1STR + k2 * 4) = hi32;
        *(uint32_t*)(im1 + 18432 + tid * W1STR + k2 * 4) = lo32;
    }
    // W2 image: rows d (0..31) x 64 j-pairs, stride 272; lo at +8704
    char* im2 = (char*)g_W2img[which];
    const int d_ = tid & 31;
    const int j2b = (tid >> 5) * 16;
    #pragma unroll 4
    for (int jj = 0; jj < 16; jj++) {
        int j2 = j2b + jj;
        float a = __ldg(W2 + (2 * j2) * D + d_);
        float b = __ldg(W2 + (2 * j2 + 1) * D + d_);
        uint32_t lo32, hi32 = split_pack(a, b, lo32);
        *(uint32_t*)(im2 + d_ * W2STR + j2 * 4) = hi32;
        *(uint32_t*)(im2 + 8704 + d_ * W2STR + j2 * 4) = lo32;
    }
}

// ---------------------------------------------------------------------------
// Half-step via warp MMA + ldmatrix + cp.async weight staging.
// ---------------------------------------------------------------------------
__global__ void __launch_bounds__(128)
half_step_mma(float* __restrict__ state,
              const float* __restrict__ tfin,
              const float* __restrict__ b2,   // (32)
              int which, int zoff, int toff,
              float tstart, float dtmax)
{
    extern __shared__ char sm[];
    const uint32_t smb = smem_u32(sm);
    const int tid  = threadIdx.x;
    const int wid  = tid >> 5;
    const int lane = tid & 31;
    const int lr   = lane >> 2;    // 0..7
    const int lq   = lane & 3;     // 0..3
    const int node_base = blockIdx.x * MT;

    // ---- stage W1 image via cp.async (overlaps gather) ----
    {
        const char* src = (const char*)g_W1img[which];
        #pragma unroll
        for (int i = 0; i < W1IMG_BYTES / 16 / 128; i++) {
            int off = (i * 128 + tid) * 16;
            CPA16(smb + W1H_OFF + off, src + off);
        }
        CPA_COMMIT();
    }

    // ---- gather X = [z(32) | mean_nbr(32)], split hi/lo (2 thr/node) ----
    {
        const int n = tid >> 1, half = tid & 1;
        const int node = node_base + n;
        const int nn_ = node & (NN - 1);
        const int r = nn_ >> 6, c = nn_ & (GRID_G - 1);
        const float* bp = state + (size_t)(node - nn_) * ROW;
        float v[32];
        if (half == 0) {
            const float4* pZ = (const float4*)(bp + (size_t)nn_ * ROW + zoff);
            #pragma unroll
            for (int i = 0; i < 8; i++) {
                float4 o = __ldg(pZ + i);
                v[4 * i] = o.x; v[4 * i + 1] = o.y;
                v[4 * i + 2] = o.z; v[4 * i + 3] = o.w;
            }
        } else {
            const int nu = (((r + GRID_G - 1) & (GRID_G - 1)) << 6) | c;
            const int nd = (((r + 1) & (GRID_G - 1)) << 6) | c;
            const int nl = (r << 6) | ((c + GRID_G - 1) & (GRID_G - 1));
            const int nr = (r << 6) | ((c + 1) & (GRID_G - 1));
            const float4* pU = (const float4*)(bp + (size_t)nu * ROW + zoff);
            const float4* pD = (const float4*)(bp + (size_t)nd * ROW + zoff);
            const float4* pL = (const float4*)(bp + (size_t)nl * ROW + zoff);
            const float4* pR = (const float4*)(bp + (size_t)nr * ROW + zoff);
            #pragma unroll
            for (int i = 0; i < 8; i++) {
                float4 a = __ldg(pU + i), b = __ldg(pD + i);
                float4 e = __ldg(pL + i), f = __ldg(pR + i);
                v[4 * i]     = 0.25f * (a.x + b.x + e.x + f.x);
                v[4 * i + 1] = 0.25f * (a.y + b.y + e.y + f.y);
                v[4 * i + 2] = 0.25f * (a.z + b.z + e.z + f.z);
                v[4 * i + 3] = 0.25f * (a.w + b.w + e.w + f.w);
            }
        }
        #pragma unroll
        for (int i = 0; i < 16; i++)
            sts_split(sm, XH_OFF + n * XSTR + half * 64 + i * 4,
                          XL_OFF + n * XSTR + half * 64 + i * 4,
                          v[2 * i], v[2 * i + 1]);
    }
    CPA_WAIT0();
    __syncthreads();

    // ---- GEMM1: per warp M64 x N32 (n0=wid*32) x K64, 3-product split ----
    float acc[4][4][4];
    #pragma unroll
    for (int a = 0; a < 4; a++)
        #pragma unroll
        for (int b = 0; b < 4; b++)
            #pragma unroll
            for (int cc = 0; cc < 4; cc++) acc[a][b][cc] = 0.0f;

    const int n0 = wid * 32;
    const uint32_t aLane = (uint32_t)((lane & 15) * XSTR + (lane >> 4) * 16);
    const uint32_t bLane = (uint32_t)((lane & 7) * W1STR + ((lane >> 3) & 1) * 16);

    #pragma unroll
    for (int kf = 0; kf < 4; kf++) {
        uint32_t ah[4][4], al[4][4];
        #pragma unroll
        for (int mf = 0; mf < 4; mf++) {
            uint32_t base = smb + mf * 16 * XSTR + kf * 32 + aLane;
            ldmx4(ah[mf], base + XH_OFF);
            ldmx4(al[mf], base + XL_OFF);
        }
        #pragma unroll
        for (int nf = 0; nf < 4; nf++) {
            uint32_t bb = smb + (n0 + nf * 8) * W1STR + kf * 32 + bLane;
            uint32_t bh[2], bl[2];
            ldmx2(bh, bb + W1H_OFF);
            ldmx2(bl, bb + W1L_OFF);
            #pragma unroll
            for (int mf = 0; mf < 4; mf++) {
                mma_bf16(acc[mf][nf], ah[mf], bh);
                mma_bf16(acc[mf][nf], al[mf], bh);
                mma_bf16(acc[mf][nf], ah[mf], bl);
            }
        }
    }
    __syncthreads();   // X/W1 dead; H/W2 overlay begins

    // ---- stage W2 image via cp.async (overlaps tanh epilogue) ----
    {
        const char* src = (const char*)g_W2img[which];
        for (int i = tid; i < W2IMG_BYTES / 16; i += 128) {
            CPA16(smb + W2H_OFF + i * 16, src + i * 16);
        }
        CPA_COMMIT();
    }

    // ---- epilogue 1: h = tanh(acc + C) -> H hi/lo smem (batched C loads) ----
    #pragma unroll
    for (int mf = 0; mf < 4; mf++) {
        int r_ = mf * 16 + lr;
        const float* Crow0 = g_C[which] + (size_t)(node_base + r_) * HID;
        const float* Crow1 = Crow0 + 8 * HID;
        float2 c01[4], c23[4];
        #pragma unroll
        for (int nf = 0; nf < 4; nf++) {
            int j = n0 + nf * 8 + lq * 2;
            c01[nf] = __ldg((const float2*)(Crow0 + j));
            c23[nf] = __ldg((const float2*)(Crow1 + j));
        }
        #pragma unroll
        for (int nf = 0; nf < 4; nf++) {
            int j = n0 + nf * 8 + lq * 2;
            float h0 = tanh_fast(acc[mf][nf][0] + c01[nf].x);
            float h1 = tanh_fast(acc[mf][nf][1] + c01[nf].y);
            float h2 = tanh_fast(acc[mf][nf][2] + c23[nf].x);
            float h3 = tanh_fast(acc[mf][nf][3] + c23[nf].y);
            sts_split(sm, HH_OFF + r_ * HSTR + j * 2,
                          HL_OFF + r_ * HSTR + j * 2, h0, h1);
            sts_split(sm, HH_OFF + (r_ + 8) * HSTR + j * 2,
                          HL_OFF + (r_ + 8) * HSTR + j * 2, h2, h3);
        }
    }
    CPA_WAIT0();
    __syncthreads();

    // ---- GEMM2: per warp M16 (r0=wid*16) x N32 x K128 ----
    float acc2[4][4];
    #pragma unroll
    for (int a = 0; a < 4; a++)
        #pragma unroll
        for (int b = 0; b < 4; b++) acc2[a][b] = 0.0f;

    const int r0 = wid * 16;
    const uint32_t aLane2 = (uint32_t)((lane & 15) * HSTR + (lane >> 4) * 16);
    const uint32_t bLane2 = (uint32_t)((lane & 7) * W2STR + ((lane >> 3) & 1) * 16);

    #pragma unroll
    for (int kf = 0; kf < 8; kf++) {
        uint32_t ah[4], al[4];
        uint32_t abase = smb + r0 * HSTR + kf * 32 + aLane2;
        ldmx4(ah, abase + HH_OFF);
        ldmx4(al, abase + HL_OFF);
        #pragma unroll
        for (int nf = 0; nf < 4; nf++) {
            uint32_t bb = smb + nf * 8 * W2STR + kf * 32 + bLane2;
            uint32_t bh[2], bl[2];
            ldmx2(bh, bb + W2H_OFF);
            ldmx2(bl, bb + W2L_OFF);
            mma_bf16(acc2[nf], ah, bh);
            mma_bf16(acc2[nf], al, bh);
            mma_bf16(acc2[nf], ah, bl);
        }
    }

    // ---- epilogue 2: state += dt * (acc2 + b2) ----
    {
        float tfv = __ldg(tfin + (node_base >> 12));
        float dtv = fminf(fmaxf(tfv - tstart, 0.0f), dtmax);
        #pragma unroll
        for (int nf = 0; nf < 4; nf++) {
            int d_ = nf * 8 + lq * 2;
            float2 bv = *(const float2*)(b2 + d_);
            int r_ = r0 + lr;
            float* p0 = state + (size_t)(node_base + r_) * ROW + toff + d_;
            float2 cur = *(float2*)p0;
            cur.x += dtv * (acc2[nf][0] + bv.x);
            cur.y += dtv * (acc2[nf][1] + bv.y);
            *(float2*)p0 = cur;
            float* p1 = state + (size_t)(node_base + r_ + 8) * ROW + toff + d_;
            cur = *(float2*)p1;
            cur.x += dtv * (acc2[nf][2] + bv.x);
            cur.y += dtv * (acc2[nf][3] + bv.y);
            *(float2*)p1 = cur;
        }
    }
}

extern "C" void kernel_launch(void* const* d_in, const int* in_sizes, int n_in,
                              void* d_out, int out_size)
{
    const float* x    = (const float*)d_in[0];
    const float* tf   = (const float*)d_in[1];
    const float* W1q  = (const float*)d_in[2];
    const float* b1q  = (const float*)d_in[3];
    const float* W2q  = (const float*)d_in[4];
    const float* b2q  = (const float*)d_in[5];
    const float* W1p  = (const float*)d_in[6];
    const float* b1p  = (const float*)d_in[7];
    const float* W2p  = (const float*)d_in[8];
    const float* b2p  = (const float*)d_in[9];
    float* state = (float*)d_out;

    cudaFuncSetAttribute(half_step_mma,
                         cudaFuncAttributeMaxDynamicSharedMemorySize, SMEM_BYTES);

    cudaMemcpyAsync(state, x, (size_t)out_size * sizeof(float),
                    cudaMemcpyDeviceToDevice);

    setup_weights<<<2, 128>>>(W1q, W2q, W1p, W2p);
    precompute_C_kernel<<<TOTAL / 128, 128>>>(x, W1q, b1q, 0);
    precompute_C_kernel<<<TOTAL / 128, 128>>>(x, W1p, b1p, 1);

    const float DT = 0.25f;

    for (int k = 0; k < 18; k++) {
        float tsq = (k == 0) ? 0.0f : (0.125f + (k - 1) * DT);
        float dmq = (k == 0) ? 0.125f : DT;
        half_step_mma<<<NCTA, 128, SMEM_BYTES>>>(
            state, tf, b2q, /*which=*/0,
            /*zoff=*/D, /*toff=*/0, tsq, dmq);

        float tsp = k * DT;
        half_step_mma<<<NCTA, 128, SMEM_BYTES>>>(
            state, tf, b2p, /*which=*/1,
            /*zoff=*/0, /*toff=*/D, tsp, DT);
    }
    (void)in_sizes; (void)n_in;
}